// round 1
// baseline (speedup 1.0000x reference)
#include <cuda_runtime.h>
#include <cuda_bf16.h>

// Problem constants (from reference): B=64, D=2048, UNITS=1024, NW=64
#define Bsz   64
#define Dd    2048
#define UNITSn 1024
#define NWn   64

// Scratch: dense effective weight W[u][i] = w[bucket(i,u)], 8 MB.
__device__ float g_W[UNITSn * Dd];

// ---------------------------------------------------------------------------
// Kernel 1: build W via per-unit shared-memory staging.
// Each half-block (256 threads) owns one unit: scatter w[k] into an smem row
// (bank-scattered, cheap), then dump the 8KB row fully coalesced.
// Every position 1..D appears exactly once per unit (idx==0 is padding).
// ---------------------------------------------------------------------------
__global__ __launch_bounds__(512) void build_w_kernel(const int* __restrict__ indices,
                                                      const float* __restrict__ w,
                                                      int L) {
    __shared__ float row[2][Dd];
    __shared__ float wsm[NWn];
    const int tid = threadIdx.x;
    const int lu  = tid >> 8;     // local unit 0/1
    const int lt  = tid & 255;
    const int u   = blockIdx.x * 2 + lu;

    if (tid < NWn) wsm[tid] = w[tid];
    #pragma unroll 8
    for (int i = lt; i < Dd; i += 256) row[lu][i] = 0.0f;
    __syncthreads();

    const int total = NWn * L;
    const long base = (long)u * total;
    for (int e = lt; e < total; e += 256) {
        int idx = __ldg(indices + base + e);
        unsigned p = (unsigned)(idx - 1);      // idx==0 -> huge, filtered
        if (p < (unsigned)Dd) row[lu][p] = wsm[e / L];
    }
    __syncthreads();

    float4*       dst = (float4*)(g_W + (long)u * Dd);
    const float4* src = (const float4*)row[lu];
    #pragma unroll
    for (int i = lt; i < Dd / 4; i += 256) dst[i] = src[i];
}

// ---------------------------------------------------------------------------
// Kernel 2: seed out with bias (out is poisoned by the harness).
// ---------------------------------------------------------------------------
__global__ void init_out_kernel(const float* __restrict__ bias, float* __restrict__ out) {
    int i = blockIdx.x * blockDim.x + threadIdx.x;
    out[i] = bias[i & (UNITSn - 1)];
}

// ---------------------------------------------------------------------------
// Kernel 3: FP32 GEMM out[b,u] += sum_k x[b,k] * W[u,k], split-K with red.add.
// Tile: BM=64 (all batches) x BN=64 units x BK=128, grid (16 unit-tiles, 16 k-splits).
// Inner product vectorized with fma.rn.f32x2 over adjacent-k pairs:
// both operands load K-contiguous (no transpose, no duplication); one
// horizontal add per accumulator at the end.
// ---------------------------------------------------------------------------
#define BKc 128
#define TSX 132   // smem row stride (floats): 16B-aligned, 2-way-conflict max

__device__ __forceinline__ void fma2(unsigned long long& d,
                                     unsigned long long a,
                                     unsigned long long b) {
    asm("fma.rn.f32x2 %0, %1, %2, %0;" : "+l"(d) : "l"(a), "l"(b));
}

__global__ __launch_bounds__(256, 2) void gemm_kernel(const float* __restrict__ x,
                                                      float* __restrict__ out) {
    extern __shared__ float sm[];
    float* xs = sm;             // [64][TSX]
    float* ws = sm + 64 * TSX;  // [64][TSX]

    const int tid = threadIdx.x;
    const int u0  = blockIdx.x * 64;
    const int k0  = blockIdx.y * BKc;

    // Cooperative load: 32 float4-columns x 8 row-groups, fully coalesced LDG.128,
    // contiguous STS.128 (conflict-free).
    {
        const int kv = tid & 31;
        const int r0 = tid >> 5;
        #pragma unroll
        for (int i = 0; i < 8; i++) {
            int b = r0 + 8 * i;
            float4 v = *(const float4*)(x + (long)b * Dd + k0 + 4 * kv);
            *(float4*)(xs + b * TSX + 4 * kv) = v;
        }
        #pragma unroll
        for (int i = 0; i < 8; i++) {
            int u = r0 + 8 * i;
            float4 v = *(const float4*)(g_W + (long)(u0 + u) * Dd + k0 + 4 * kv);
            *(float4*)(ws + u * TSX + 4 * kv) = v;
        }
    }
    __syncthreads();

    const int tx = tid & 15;   // unit lane: units {tx, tx+16, tx+32, tx+48}
    const int ty = tid >> 4;   // batch group: batches {4ty .. 4ty+3}

    unsigned long long acc[4][4];
    #pragma unroll
    for (int i = 0; i < 4; i++)
        #pragma unroll
        for (int j = 0; j < 4; j++) acc[i][j] = 0ULL;  // (0.0f, 0.0f)

    #pragma unroll 4
    for (int kk = 0; kk < BKc; kk += 4) {
        ulonglong2 xv[4], wv[4];
        #pragma unroll
        for (int i = 0; i < 4; i++)
            xv[i] = *(const ulonglong2*)(xs + (4 * ty + i) * TSX + kk);
        #pragma unroll
        for (int j = 0; j < 4; j++)
            wv[j] = *(const ulonglong2*)(ws + (tx + 16 * j) * TSX + kk);
        #pragma unroll
        for (int i = 0; i < 4; i++)
            #pragma unroll
            for (int j = 0; j < 4; j++) {
                fma2(acc[i][j], xv[i].x, wv[j].x);  // k, k+1
                fma2(acc[i][j], xv[i].y, wv[j].y);  // k+2, k+3
            }
    }

    // Horizontal add of the f32x2 halves, then split-K reduction via red.add.
    #pragma unroll
    for (int i = 0; i < 4; i++)
        #pragma unroll
        for (int j = 0; j < 4; j++) {
            unsigned long long v = acc[i][j];
            float lo = __uint_as_float((unsigned)(v & 0xffffffffu));
            float hi = __uint_as_float((unsigned)(v >> 32));
            atomicAdd(out + (long)(4 * ty + i) * UNITSn + u0 + tx + 16 * j, lo + hi);
        }
}

// ---------------------------------------------------------------------------
// Launch: init(out=bias) ; build_w ; gemm   (single stream => ordered)
// ---------------------------------------------------------------------------
extern "C" void kernel_launch(void* const* d_in, const int* in_sizes, int n_in,
                              void* d_out, int out_size) {
    const float* x       = (const float*)d_in[0];
    const float* w       = (const float*)d_in[1];
    const float* bias    = (const float*)d_in[2];
    const int*   indices = (const int*)d_in[3];
    float*       out     = (float*)d_out;

    const int L = in_sizes[3] / (UNITSn * NWn);

    const int smem_bytes = 2 * 64 * TSX * (int)sizeof(float);  // 67,584 B
    cudaFuncSetAttribute(gemm_kernel, cudaFuncAttributeMaxDynamicSharedMemorySize,
                         smem_bytes);

    init_out_kernel<<<(Bsz * UNITSn) / 256, 256>>>(bias, out);
    build_w_kernel<<<UNITSn / 2, 512>>>(indices, w, L);
    gemm_kernel<<<dim3(UNITSn / 64, Dd / BKc), 256, smem_bytes>>>(x, out);
}

// round 2
// speedup vs baseline: 1.0577x; 1.0577x over previous
#include <cuda_runtime.h>
#include <cuda_bf16.h>

// Problem constants: B=64, D=2048, UNITS=1024, NW=64
#define Bsz    64
#define Dd     2048
#define UNITSn 1024
#define NWn    64

// Scratch: dense effective weight W[u][i] = w[bucket(i,u)], 8 MB.
__device__ float g_W[UNITSn * Dd];

// ---------------------------------------------------------------------------
// Kernel 1: build W via per-unit shared-memory staging, AND seed out with
// bias (fused here to save a launch; runs before gemm in stream order).
// Each half-block (256 threads) owns one unit: scatter w[k] into an smem row,
// then dump the 8KB row fully coalesced. idx==0 is padding (zero column).
// ---------------------------------------------------------------------------
__global__ __launch_bounds__(512) void build_w_kernel(const int* __restrict__ indices,
                                                      const float* __restrict__ w,
                                                      const float* __restrict__ bias,
                                                      float* __restrict__ out,
                                                      int L) {
    __shared__ float row[2][Dd];
    __shared__ float wsm[NWn];
    const int tid = threadIdx.x;
    const int lu  = tid >> 8;     // local unit 0/1
    const int lt  = tid & 255;
    const int u   = blockIdx.x * 2 + lu;

    // Fused bias init: 512 blocks x 128 elements = 65536 = B*UNITS.
    if (tid < 128) {
        int g = blockIdx.x * 128 + tid;
        out[g] = bias[g & (UNITSn - 1)];
    }

    if (tid < NWn) wsm[tid] = w[tid];
    #pragma unroll 8
    for (int i = lt; i < Dd; i += 256) row[lu][i] = 0.0f;
    __syncthreads();

    const int total = NWn * L;
    const long base = (long)u * total;
    for (int e = lt; e < total; e += 256) {
        int idx = __ldg(indices + base + e);
        unsigned p = (unsigned)(idx - 1);      // idx==0 -> huge, filtered
        if (p < (unsigned)Dd) row[lu][p] = wsm[e / L];
    }
    __syncthreads();

    float4*       dst = (float4*)(g_W + (long)u * Dd);
    const float4* src = (const float4*)row[lu];
    #pragma unroll
    for (int i = lt; i < Dd / 4; i += 256) dst[i] = src[i];
}

// ---------------------------------------------------------------------------
// Kernel 2: FP32 split-K GEMM  out[b,u] += sum_k x[b,k] * W[u,k]
// BM=64 (all batches) x BN=128 units x BK=128, grid (8 unit-tiles, 16 k-splits)
// = 128 CTAs (~1/SM). 128 threads, 8x8 register tile per thread with
// fma.rn.f32x2 along k (1 smem-byte per FMA -> fma-issue bound, not LDS).
// Partials land via red.global.add.f32 on the bias-seeded out.
// ---------------------------------------------------------------------------
#define BKc 128
#define BNc 128
#define TSX 132   // smem row stride (floats): 16B aligned, <=2-way conflicts

__device__ __forceinline__ void fma2(unsigned long long& d,
                                     unsigned long long a,
                                     unsigned long long b) {
    asm("fma.rn.f32x2 %0, %1, %2, %0;" : "+l"(d) : "l"(a), "l"(b));
}

__global__ __launch_bounds__(128) void gemm_kernel(const float* __restrict__ x,
                                                   float* __restrict__ out) {
    extern __shared__ float sm[];
    float* xs = sm;               // [64][TSX]
    float* ws = sm + 64 * TSX;    // [BNc][TSX]

    const int tid = threadIdx.x;
    const int u0  = blockIdx.x * BNc;
    const int k0  = blockIdx.y * BKc;

    // Cooperative load: 32 float4-columns x 4 row-groups per warp-lane split.
    // LDG.128 coalesced (512B/row-chunk), STS.128 contiguous (conflict-free).
    {
        const int kv = tid & 31;      // float4 column within BK
        const int r0 = tid >> 5;      // row group 0..3
        #pragma unroll
        for (int i = 0; i < 16; i++) {
            int b = r0 + 4 * i;
            float4 v = *(const float4*)(x + (long)b * Dd + k0 + 4 * kv);
            *(float4*)(xs + b * TSX + 4 * kv) = v;
        }
        #pragma unroll
        for (int i = 0; i < 32; i++) {
            int u = r0 + 4 * i;
            float4 v = *(const float4*)(g_W + (long)(u0 + u) * Dd + k0 + 4 * kv);
            *(float4*)(ws + u * TSX + 4 * kv) = v;
        }
    }
    __syncthreads();

    const int tx = tid & 15;   // unit lane: units {tx + 16j, j=0..7}
    const int ty = tid >> 4;   // batch lane: batches {8ty + i, i=0..7}

    unsigned long long acc[8][8];
    #pragma unroll
    for (int i = 0; i < 8; i++)
        #pragma unroll
        for (int j = 0; j < 8; j++) acc[i][j] = 0ULL;   // (0.0f, 0.0f)

    const float* xbase = xs + ty * 8 * TSX;
    const float* wbase = ws + tx * TSX;

    #pragma unroll 2
    for (int kk = 0; kk < BKc; kk += 2) {
        unsigned long long xv[8], wv[8];
        #pragma unroll
        for (int i = 0; i < 8; i++)
            xv[i] = *(const unsigned long long*)(xbase + i * TSX + kk);
        #pragma unroll
        for (int j = 0; j < 8; j++)
            wv[j] = *(const unsigned long long*)(wbase + j * 16 * TSX + kk);
        #pragma unroll
        for (int i = 0; i < 8; i++)
            #pragma unroll
            for (int j = 0; j < 8; j++)
                fma2(acc[i][j], xv[i], wv[j]);
    }

    // Horizontal add of f32x2 halves, split-K reduction via red.global.add.
    #pragma unroll
    for (int i = 0; i < 8; i++) {
        float* orow = out + (long)(ty * 8 + i) * UNITSn + u0 + tx;
        #pragma unroll
        for (int j = 0; j < 8; j++) {
            unsigned long long v = acc[i][j];
            float lo = __uint_as_float((unsigned)(v & 0xffffffffu));
            float hi = __uint_as_float((unsigned)(v >> 32));
            atomicAdd(orow + 16 * j, lo + hi);
        }
    }
}

// ---------------------------------------------------------------------------
// Launch: build_w (also seeds out=bias) ; gemm   (single stream => ordered)
// ---------------------------------------------------------------------------
extern "C" void kernel_launch(void* const* d_in, const int* in_sizes, int n_in,
                              void* d_out, int out_size) {
    const float* x       = (const float*)d_in[0];
    const float* w       = (const float*)d_in[1];
    const float* bias    = (const float*)d_in[2];
    const int*   indices = (const int*)d_in[3];
    float*       out     = (float*)d_out;

    const int L = in_sizes[3] / (UNITSn * NWn);

    const int smem_bytes = (64 + BNc) * TSX * (int)sizeof(float);  // 101,376 B
    cudaFuncSetAttribute(gemm_kernel, cudaFuncAttributeMaxDynamicSharedMemorySize,
                         smem_bytes);

    build_w_kernel<<<UNITSn / 2, 512>>>(indices, w, bias, out, L);
    gemm_kernel<<<dim3(UNITSn / BNc, Dd / BKc), 128, smem_bytes>>>(x, out);
}